// round 10
// baseline (speedup 1.0000x reference)
#include <cuda_runtime.h>
#include <cuda_bf16.h>
#include <cstdint>

// Problem constants
#define B_ 128
#define H_ 512
#define I_ 512
#define SIXH 3072
#define BH (B_ * H_)          // 65536
#define CSZ (B_ * H_ * H_)    // 33554432
#define NSPLIT 6
#define NCHUNK 4
#define MCHUNK 32             // batches per chunk

// ---------------- scratch (no allocs allowed) ----------------
__device__ float g_part[NSPLIT][B_ * SIXH];   // split-K partial gates
__device__ float g_f[BH];
__device__ float g_add[BH];
__device__ float g_o[BH];
__device__ float g_q[BH];
__device__ float g_denom[B_];

// ---------------- Kernel 1: chunk partial gates = x @ W^T (fp32, split-K=6) --
// Per chunk: M=32(batch slice), N=3072, K=512. NT gemm, both K-major.
// Tile 32x128, BK=16, 128 threads (4 warps, warp tile 32x32), micro 4x8,
// double-buffered smem. Grid (24, 6) = 144 blocks per chunk.
#define GBM 32
#define GBN 128
#define GBK 16

__global__ __launch_bounds__(128) void gemm_kernel(
    const float* __restrict__ x,      // [128,512]
    const float* __restrict__ W,      // [3072,512]
    const int mbase)                  // chunk batch offset
{
    __shared__ float sA[2][GBK][GBM + 4];   // 4.6 KB
    __shared__ float sB[2][GBK][GBN + 4];   // 16.9 KB

    const int bn = blockIdx.x * GBN;
    const int z  = blockIdx.y;                        // 0..5
    const int k_lo = (z < 4) ? z * 96 : 384 + (z - 4) * 64;
    const int nkt  = (z < 4) ? 6 : 4;

    const int t    = threadIdx.x;
    const int wid  = t >> 5;
    const int lane = t & 31;
    const int mt   = (lane & 7) * 4;      // 4 rows
    const int nt   = (lane >> 3) * 8;     // 8 cols
    const int bcol = wid * 32 + nt;

    // loaders: A 32x16 -> 1 float4/thread; B 128x16 -> 4 float4/thread
    const int lr = t >> 2;                // 0..31
    const int lk = (t & 3) * 4;           // 0,4,8,12

    const float* pA = x + (size_t)(mbase + lr) * I_ + k_lo + lk;
    const float* pB = W + (size_t)(bn + lr) * I_ + k_lo + lk;

    float4 ra, rb[4];

    // prologue: tile0 -> buf0
    ra = __ldg((const float4*)pA);
    #pragma unroll
    for (int i = 0; i < 4; i++) rb[i] = __ldg((const float4*)(pB + (size_t)i * 32 * I_));
    sA[0][lk + 0][lr] = ra.x; sA[0][lk + 1][lr] = ra.y; sA[0][lk + 2][lr] = ra.z; sA[0][lk + 3][lr] = ra.w;
    #pragma unroll
    for (int i = 0; i < 4; i++) {
        sB[0][lk + 0][lr + i * 32] = rb[i].x; sB[0][lk + 1][lr + i * 32] = rb[i].y;
        sB[0][lk + 2][lr + i * 32] = rb[i].z; sB[0][lk + 3][lr + i * 32] = rb[i].w;
    }
    // prefetch tile1 -> regs
    ra = __ldg((const float4*)(pA + GBK));
    #pragma unroll
    for (int i = 0; i < 4; i++) rb[i] = __ldg((const float4*)(pB + (size_t)i * 32 * I_ + GBK));
    __syncthreads();

    float acc[4][8] = {};

    for (int kt = 0; kt < nkt; kt++) {
        const int cur = kt & 1;
        if (kt < nkt - 1) {
            const int nxt = 1 - cur;
            sA[nxt][lk + 0][lr] = ra.x; sA[nxt][lk + 1][lr] = ra.y; sA[nxt][lk + 2][lr] = ra.z; sA[nxt][lk + 3][lr] = ra.w;
            #pragma unroll
            for (int i = 0; i < 4; i++) {
                sB[nxt][lk + 0][lr + i * 32] = rb[i].x; sB[nxt][lk + 1][lr + i * 32] = rb[i].y;
                sB[nxt][lk + 2][lr + i * 32] = rb[i].z; sB[nxt][lk + 3][lr + i * 32] = rb[i].w;
            }
            if (kt < nkt - 2) {
                const int ko = (kt + 2) * GBK;
                ra = __ldg((const float4*)(pA + ko));
                #pragma unroll
                for (int i = 0; i < 4; i++) rb[i] = __ldg((const float4*)(pB + (size_t)i * 32 * I_ + ko));
            }
        }

        #pragma unroll
        for (int k = 0; k < GBK; k++) {
            float4 av  = *reinterpret_cast<const float4*>(&sA[cur][k][mt]);
            float4 bv0 = *reinterpret_cast<const float4*>(&sB[cur][k][bcol]);
            float4 bv1 = *reinterpret_cast<const float4*>(&sB[cur][k][bcol + 4]);
            float a[4] = {av.x, av.y, av.z, av.w};
            float b[8] = {bv0.x, bv0.y, bv0.z, bv0.w, bv1.x, bv1.y, bv1.z, bv1.w};
            #pragma unroll
            for (int i = 0; i < 4; i++)
                #pragma unroll
                for (int j = 0; j < 8; j++)
                    acc[i][j] = fmaf(a[i], b[j], acc[i][j]);
        }
        __syncthreads();
    }

    float* out = g_part[z];
    #pragma unroll
    for (int i = 0; i < 4; i++) {
        float* row = out + (size_t)(mbase + mt + i) * SIXH + bn + bcol;
        *reinterpret_cast<float4*>(row)     = make_float4(acc[i][0], acc[i][1], acc[i][2], acc[i][3]);
        *reinterpret_cast<float4*>(row + 4) = make_float4(acc[i][4], acc[i][5], acc[i][6], acc[i][7]);
    }
}

// ---------------- Kernel 2: gate transforms + n.q reduction (per chunk) --------
__global__ __launch_bounds__(512) void gate_kernel(
    const float* __restrict__ m_prev,
    const float* __restrict__ n_prev,
    const float* __restrict__ bias,
    float* __restrict__ out_m,
    float* __restrict__ out_n,
    const int mbase)
{
    const int b = mbase + blockIdx.x;
    const int h = threadIdx.x;
    const int base = b * SIXH;

    float g[6];
    #pragma unroll
    for (int gi = 0; gi < 6; gi++) {
        int off = base + gi * H_ + h;
        float s01 = g_part[0][off] + g_part[1][off];
        float s23 = g_part[2][off] + g_part[3][off];
        float s45 = g_part[4][off] + g_part[5][off];
        g[gi] = ((s01 + s23) + s45) + bias[gi * H_ + h];
    }
    float ig = g[0], fg = g[1], og = g[2], qv = g[3], kk = g[4], vv = g[5];

    const int idx = b * H_ + h;
    float mp = m_prev[idx];
    float mt = fmaxf(fg + mp, ig);
    float it = expf(ig - mt);
    float ft = expf(fg + mp - mt);
    float kt = 0.04419417382415922f * kk;   // 1/sqrt(512)
    float nt = ft * n_prev[idx] + it * kt;

    out_m[idx] = mt;
    out_n[idx] = nt;
    g_f[idx]   = ft;
    g_add[idx] = it * vv * kt;
    g_o[idx]   = 1.0f / (1.0f + expf(-og));
    g_q[idx]   = qv;

    float s = nt * qv;
    #pragma unroll
    for (int off = 16; off; off >>= 1) s += __shfl_xor_sync(0xffffffffu, s, off);

    __shared__ float red[16];
    int w = threadIdx.x >> 5, lane = threadIdx.x & 31;
    if (lane == 0) red[w] = s;
    __syncthreads();
    if (threadIdx.x == 0) {
        float tsum = 0.f;
        #pragma unroll
        for (int i = 0; i < 16; i++) tsum += red[i];
        g_denom[b] = fmaxf(fabsf(tsum), 1e-6f);
    }
}

// ---------------- Kernel 3: C_t update + readout + h_t (per chunk) ------------
__global__ __launch_bounds__(256) void cmain_kernel(
    const float* __restrict__ C_prev,
    float* __restrict__ out_C,
    float* __restrict__ out_h,
    const int mbase)
{
    __shared__ float sq[H_];
    const int b = mbase + (blockIdx.x >> 6);  // 64 blocks per batch
    const int row0 = (blockIdx.x & 63) * 8;

    const float* q = g_q + b * H_;
    for (int h = threadIdx.x; h < H_; h += 256) sq[h] = q[h];
    __syncthreads();

    const int w = threadIdx.x >> 5;
    const int lane = threadIdx.x & 31;
    const int i = row0 + w;
    const int bi = b * H_ + i;

    const float f   = g_f[bi];
    const float add = g_add[bi];

    const float4* Cp = reinterpret_cast<const float4*>(C_prev) + (size_t)bi * (H_ / 4);
    float4*       Co = reinterpret_cast<float4*>(out_C)        + (size_t)bi * (H_ / 4);
    const float4* q4 = reinterpret_cast<const float4*>(sq);

    float4 c[4];
    #pragma unroll
    for (int t = 0; t < 4; t++) c[t] = __ldcs(Cp + lane + t * 32);

    float acc = 0.f;
    #pragma unroll
    for (int t = 0; t < 4; t++) {
        int j4 = lane + t * 32;
        float4 r;
        r.x = fmaf(f, c[t].x, add);
        r.y = fmaf(f, c[t].y, add);
        r.z = fmaf(f, c[t].z, add);
        r.w = fmaf(f, c[t].w, add);
        __stcs(Co + j4, r);
        float4 qq = q4[j4];
        acc += r.x * qq.x + r.y * qq.y + r.z * qq.z + r.w * qq.w;
    }

    #pragma unroll
    for (int off = 16; off; off >>= 1) acc += __shfl_xor_sync(0xffffffffu, acc, off);

    if (lane == 0)
        out_h[bi] = g_o[bi] * acc / g_denom[b];
}

// ---------------- streams/events (host-side objects, created at load) ---------
struct HxPipe {
    cudaStream_t sc, sm;
    cudaEvent_t eFork, eGate[NCHUNK], eJoinC, eJoinM;
    HxPipe() {
        cudaStreamCreateWithFlags(&sc, cudaStreamNonBlocking);
        cudaStreamCreateWithFlags(&sm, cudaStreamNonBlocking);
        cudaEventCreateWithFlags(&eFork, cudaEventDisableTiming);
        for (int i = 0; i < NCHUNK; i++)
            cudaEventCreateWithFlags(&eGate[i], cudaEventDisableTiming);
        cudaEventCreateWithFlags(&eJoinC, cudaEventDisableTiming);
        cudaEventCreateWithFlags(&eJoinM, cudaEventDisableTiming);
    }
};
static HxPipe g_px;

// ---------------- launch: 2-stream chunked pipeline ---------------------------
extern "C" void kernel_launch(void* const* d_in, const int* in_sizes, int n_in,
                              void* d_out, int out_size)
{
    const float* x      = (const float*)d_in[0];
    // d_in[1] = h_prev (unused by the reference)
    const float* C_prev = (const float*)d_in[2];
    const float* m_prev = (const float*)d_in[3];
    const float* n_prev = (const float*)d_in[4];
    const float* W      = (const float*)d_in[5];
    const float* bias   = (const float*)d_in[6];

    float* out   = (float*)d_out;
    float* out_h = out;                       // [B,H]
    float* out_C = out + BH;                  // [B,H,H]
    float* out_m = out + BH + CSZ;            // [B,H]
    float* out_n = out + BH + CSZ + BH;       // [B,H]

    // fork both worker streams off the capture (legacy) stream
    cudaEventRecord(g_px.eFork, 0);
    cudaStreamWaitEvent(g_px.sc, g_px.eFork, 0);
    cudaStreamWaitEvent(g_px.sm, g_px.eFork, 0);

    for (int c = 0; c < NCHUNK; c++) {
        const int mbase = c * MCHUNK;
        dim3 gg(SIXH / GBN, NSPLIT);          // (24, 6) = 144 blocks
        gemm_kernel<<<gg, 128, 0, g_px.sc>>>(x, W, mbase);
        gate_kernel<<<MCHUNK, 512, 0, g_px.sc>>>(m_prev, n_prev, bias, out_m, out_n, mbase);
        cudaEventRecord(g_px.eGate[c], g_px.sc);
        cudaStreamWaitEvent(g_px.sm, g_px.eGate[c], 0);
        cmain_kernel<<<MCHUNK * 64, 256, 0, g_px.sm>>>(C_prev, out_C, out_h, mbase);
    }

    // join both streams back into the capture stream
    cudaEventRecord(g_px.eJoinC, g_px.sc);
    cudaEventRecord(g_px.eJoinM, g_px.sm);
    cudaStreamWaitEvent((cudaStream_t)0, g_px.eJoinC, 0);
    cudaStreamWaitEvent((cudaStream_t)0, g_px.eJoinM, 0);
}

// round 11
// speedup vs baseline: 1.7977x; 1.7977x over previous
#include <cuda_runtime.h>
#include <cuda_bf16.h>
#include <cstdint>

// Problem constants
#define B_ 128
#define H_ 512
#define I_ 512
#define SIXH 3072
#define BH (B_ * H_)          // 65536
#define CSZ (B_ * H_ * H_)    // 33554432
#define NSPLIT 6

// ---------------- scratch (no allocs allowed) ----------------
__device__ float g_part[NSPLIT][B_ * SIXH];   // split-K partial gates
__device__ float g_f[BH];
__device__ float g_add[BH];
__device__ float g_o[BH];
__device__ float g_q[BH];
__device__ float g_denom[B_];

// ---------------- Kernel 1: partial gates = x @ W^T (fp32 FFMA, split-K=6) ----
// M=128(b)=BM, N=3072(gate), K=512. NT gemm, both operands K-major.
// BM=128 x BN=64 tile, BK=16, 128 threads (4 warps), micro-tile 8x8,
// double-buffered smem, one barrier per k-tile.
// Grid (48, 6) = 288 blocks ~= 2 resident blocks per SM (latency interleave).
#define GBM 128
#define GBN 64
#define GBK 16

__global__ __launch_bounds__(128) void gemm_kernel(
    const float* __restrict__ x,      // [128,512]
    const float* __restrict__ W)      // [3072,512]
{
    __shared__ float sA[2][GBK][GBM + 4];   // 16.9 KB
    __shared__ float sB[2][GBK][GBN + 4];   // 8.7 KB

    const int bn = blockIdx.x * GBN;
    const int z  = blockIdx.y;                        // 0..5
    // k split: z<4 -> 96 wide, z>=4 -> 64 wide  (4*96 + 2*64 = 512)
    const int k_lo = (z < 4) ? z * 96 : 384 + (z - 4) * 64;
    const int nkt  = (z < 4) ? 6 : 4;                 // k-tiles of 16

    const int t = threadIdx.x;
    // compute mapping: 16 (m) x 8 (n) thread grid, micro-tile 8x8
    const int arow = (t >> 3) * 8;        // 0..120
    const int bcol = (t & 7) * 8;         // 0..56

    // loaders:
    //  A tile 128x16 = 512 float4: thread t loads row t, 4 float4 (k 0,4,8,12)
    //  B tile  64x16 = 256 float4: thread t loads row t>>1, 2 float4 at (t&1)*8
    const int brow = t >> 1;
    const int bk   = (t & 1) * 8;

    const float* pA = x + (size_t)t * I_ + k_lo;
    const float* pB = W + (size_t)(bn + brow) * I_ + k_lo + bk;

    float4 a0, a1, a2, a3, b0, b1;

    // prologue: tile0 -> buf0
    a0 = __ldg((const float4*)(pA + 0));
    a1 = __ldg((const float4*)(pA + 4));
    a2 = __ldg((const float4*)(pA + 8));
    a3 = __ldg((const float4*)(pA + 12));
    b0 = __ldg((const float4*)(pB + 0));
    b1 = __ldg((const float4*)(pB + 4));
    sA[0][ 0][t] = a0.x; sA[0][ 1][t] = a0.y; sA[0][ 2][t] = a0.z; sA[0][ 3][t] = a0.w;
    sA[0][ 4][t] = a1.x; sA[0][ 5][t] = a1.y; sA[0][ 6][t] = a1.z; sA[0][ 7][t] = a1.w;
    sA[0][ 8][t] = a2.x; sA[0][ 9][t] = a2.y; sA[0][10][t] = a2.z; sA[0][11][t] = a2.w;
    sA[0][12][t] = a3.x; sA[0][13][t] = a3.y; sA[0][14][t] = a3.z; sA[0][15][t] = a3.w;
    sB[0][bk + 0][brow] = b0.x; sB[0][bk + 1][brow] = b0.y; sB[0][bk + 2][brow] = b0.z; sB[0][bk + 3][brow] = b0.w;
    sB[0][bk + 4][brow] = b1.x; sB[0][bk + 5][brow] = b1.y; sB[0][bk + 6][brow] = b1.z; sB[0][bk + 7][brow] = b1.w;
    // prefetch tile1 -> regs
    a0 = __ldg((const float4*)(pA + GBK + 0));
    a1 = __ldg((const float4*)(pA + GBK + 4));
    a2 = __ldg((const float4*)(pA + GBK + 8));
    a3 = __ldg((const float4*)(pA + GBK + 12));
    b0 = __ldg((const float4*)(pB + GBK + 0));
    b1 = __ldg((const float4*)(pB + GBK + 4));
    __syncthreads();

    float acc[8][8] = {};

    for (int kt = 0; kt < nkt; kt++) {
        const int cur = kt & 1;
        if (kt < nkt - 1) {
            const int nxt = 1 - cur;
            sA[nxt][ 0][t] = a0.x; sA[nxt][ 1][t] = a0.y; sA[nxt][ 2][t] = a0.z; sA[nxt][ 3][t] = a0.w;
            sA[nxt][ 4][t] = a1.x; sA[nxt][ 5][t] = a1.y; sA[nxt][ 6][t] = a1.z; sA[nxt][ 7][t] = a1.w;
            sA[nxt][ 8][t] = a2.x; sA[nxt][ 9][t] = a2.y; sA[nxt][10][t] = a2.z; sA[nxt][11][t] = a2.w;
            sA[nxt][12][t] = a3.x; sA[nxt][13][t] = a3.y; sA[nxt][14][t] = a3.z; sA[nxt][15][t] = a3.w;
            sB[nxt][bk + 0][brow] = b0.x; sB[nxt][bk + 1][brow] = b0.y; sB[nxt][bk + 2][brow] = b0.z; sB[nxt][bk + 3][brow] = b0.w;
            sB[nxt][bk + 4][brow] = b1.x; sB[nxt][bk + 5][brow] = b1.y; sB[nxt][bk + 6][brow] = b1.z; sB[nxt][bk + 7][brow] = b1.w;
            if (kt < nkt - 2) {
                const int ko = (kt + 2) * GBK;
                a0 = __ldg((const float4*)(pA + ko + 0));
                a1 = __ldg((const float4*)(pA + ko + 4));
                a2 = __ldg((const float4*)(pA + ko + 8));
                a3 = __ldg((const float4*)(pA + ko + 12));
                b0 = __ldg((const float4*)(pB + ko + 0));
                b1 = __ldg((const float4*)(pB + ko + 4));
            }
        }

        #pragma unroll
        for (int k = 0; k < GBK; k++) {
            float4 av0 = *reinterpret_cast<const float4*>(&sA[cur][k][arow]);
            float4 av1 = *reinterpret_cast<const float4*>(&sA[cur][k][arow + 4]);
            float4 bv0 = *reinterpret_cast<const float4*>(&sB[cur][k][bcol]);
            float4 bv1 = *reinterpret_cast<const float4*>(&sB[cur][k][bcol + 4]);
            float a[8] = {av0.x, av0.y, av0.z, av0.w, av1.x, av1.y, av1.z, av1.w};
            float b[8] = {bv0.x, bv0.y, bv0.z, bv0.w, bv1.x, bv1.y, bv1.z, bv1.w};
            #pragma unroll
            for (int i = 0; i < 8; i++)
                #pragma unroll
                for (int j = 0; j < 8; j++)
                    acc[i][j] = fmaf(a[i], b[j], acc[i][j]);
        }
        __syncthreads();
    }

    float* out = g_part[z];
    #pragma unroll
    for (int i = 0; i < 8; i++) {
        float* row = out + (size_t)(arow + i) * SIXH + bn + bcol;
        *reinterpret_cast<float4*>(row)     = make_float4(acc[i][0], acc[i][1], acc[i][2], acc[i][3]);
        *reinterpret_cast<float4*>(row + 4) = make_float4(acc[i][4], acc[i][5], acc[i][6], acc[i][7]);
    }
}

// ---------------- Kernel 2: gate transforms + n.q reduction (fused) ----------------
// One block per batch b, 512 threads (one per h). gate order: ig,fg,og,q,k,v.
__global__ __launch_bounds__(512) void gate_kernel(
    const float* __restrict__ m_prev,
    const float* __restrict__ n_prev,
    const float* __restrict__ bias,
    float* __restrict__ out_m,
    float* __restrict__ out_n)
{
    const int b = blockIdx.x;
    const int h = threadIdx.x;
    const int base = b * SIXH;

    float g[6];
    #pragma unroll
    for (int gi = 0; gi < 6; gi++) {
        int off = base + gi * H_ + h;
        float s01 = g_part[0][off] + g_part[1][off];
        float s23 = g_part[2][off] + g_part[3][off];
        float s45 = g_part[4][off] + g_part[5][off];
        g[gi] = ((s01 + s23) + s45) + bias[gi * H_ + h];
    }
    float ig = g[0], fg = g[1], og = g[2], qv = g[3], kk = g[4], vv = g[5];

    const int idx = b * H_ + h;
    float mp = m_prev[idx];
    float mt = fmaxf(fg + mp, ig);
    float it = expf(ig - mt);
    float ft = expf(fg + mp - mt);
    float kt = 0.04419417382415922f * kk;   // 1/sqrt(512)
    float nt = ft * n_prev[idx] + it * kt;

    out_m[idx] = mt;
    out_n[idx] = nt;
    g_f[idx]   = ft;
    g_add[idx] = it * vv * kt;
    g_o[idx]   = 1.0f / (1.0f + expf(-og));
    g_q[idx]   = qv;

    // deterministic block reduce of nt*qv over 512 threads
    float s = nt * qv;
    #pragma unroll
    for (int off = 16; off; off >>= 1) s += __shfl_xor_sync(0xffffffffu, s, off);

    __shared__ float red[16];
    int w = threadIdx.x >> 5, lane = threadIdx.x & 31;
    if (lane == 0) red[w] = s;
    __syncthreads();
    if (threadIdx.x == 0) {
        float tsum = 0.f;
        #pragma unroll
        for (int i = 0; i < 16; i++) tsum += red[i];
        g_denom[b] = fmaxf(fabsf(tsum), 1e-6f);
    }
}

// ---------------- Kernel 3: C_t update + readout + h_t ----------------
// One warp per (b,i) row of 512 floats; 8 warps per block; q[b] staged in smem.
// C_prev / out_C are touch-once streams -> evict-first (ldcs/stcs).
__global__ __launch_bounds__(256) void cmain_kernel(
    const float* __restrict__ C_prev,
    float* __restrict__ out_C,
    float* __restrict__ out_h)
{
    __shared__ float sq[H_];
    const int b = blockIdx.x >> 6;            // 64 blocks per batch
    const int row0 = (blockIdx.x & 63) * 8;

    const float* q = g_q + b * H_;
    for (int h = threadIdx.x; h < H_; h += 256) sq[h] = q[h];
    __syncthreads();

    const int w = threadIdx.x >> 5;
    const int lane = threadIdx.x & 31;
    const int i = row0 + w;
    const int bi = b * H_ + i;

    const float f   = g_f[bi];
    const float add = g_add[bi];

    const float4* Cp = reinterpret_cast<const float4*>(C_prev) + (size_t)bi * (H_ / 4);
    float4*       Co = reinterpret_cast<float4*>(out_C)        + (size_t)bi * (H_ / 4);
    const float4* q4 = reinterpret_cast<const float4*>(sq);

    float4 c[4];
    #pragma unroll
    for (int t = 0; t < 4; t++) c[t] = __ldcs(Cp + lane + t * 32);

    float acc = 0.f;
    #pragma unroll
    for (int t = 0; t < 4; t++) {
        int j4 = lane + t * 32;
        float4 r;
        r.x = fmaf(f, c[t].x, add);
        r.y = fmaf(f, c[t].y, add);
        r.z = fmaf(f, c[t].z, add);
        r.w = fmaf(f, c[t].w, add);
        __stcs(Co + j4, r);
        float4 qq = q4[j4];
        acc += r.x * qq.x + r.y * qq.y + r.z * qq.z + r.w * qq.w;
    }

    #pragma unroll
    for (int off = 16; off; off >>= 1) acc += __shfl_xor_sync(0xffffffffu, acc, off);

    if (lane == 0)
        out_h[bi] = g_o[bi] * acc / g_denom[b];
}

// ---------------- launch: serial single-stream (R10 showed overlap regresses) --
extern "C" void kernel_launch(void* const* d_in, const int* in_sizes, int n_in,
                              void* d_out, int out_size)
{
    const float* x      = (const float*)d_in[0];
    // d_in[1] = h_prev (unused by the reference)
    const float* C_prev = (const float*)d_in[2];
    const float* m_prev = (const float*)d_in[3];
    const float* n_prev = (const float*)d_in[4];
    const float* W      = (const float*)d_in[5];
    const float* bias   = (const float*)d_in[6];

    float* out   = (float*)d_out;
    float* out_h = out;                       // [B,H]
    float* out_C = out + BH;                  // [B,H,H]
    float* out_m = out + BH + CSZ;            // [B,H]
    float* out_n = out + BH + CSZ + BH;       // [B,H]

    dim3 ggrid(SIXH / GBN, NSPLIT);           // (48, 6) = 288 blocks ~ 2/SM
    gemm_kernel<<<ggrid, 128>>>(x, W);

    gate_kernel<<<B_, 512>>>(m_prev, n_prev, bias, out_m, out_n);

    cmain_kernel<<<B_ * 64, 256>>>(C_prev, out_C, out_h);
}

// round 13
// speedup vs baseline: 1.8636x; 1.0367x over previous
#include <cuda_runtime.h>
#include <cuda_bf16.h>
#include <cstdint>

// Problem constants
#define B_ 128
#define H_ 512
#define I_ 512
#define SIXH 3072
#define BH (B_ * H_)          // 65536
#define CSZ (B_ * H_ * H_)    // 33554432
#define NSPLIT 6

// ---------------- scratch (no allocs allowed) ----------------
__device__ float g_part[NSPLIT][B_ * SIXH];   // split-K partial gates
__device__ float g_f[BH];
__device__ float g_add[BH];
__device__ float g_o[BH];
__device__ float g_q[BH];
__device__ float g_denom[B_];

// ---------------- Kernel 1: partial gates = x @ W^T (fp32 FFMA, split-K=6) ----
// M=128(b)=BM, N=3072(gate), K=512. NT gemm, both operands K-major.
// BM=128 x BN=128 tile, BK=16, 256 threads (8 warps), micro-tile 8x8,
// double-buffered smem, one barrier per k-tile.
// Grid (24, 6) = 144 blocks = one wave. Balanced splits: 2x96 + 4x80.
#define GBM 128
#define GBN 128
#define GBK 16

__global__ __launch_bounds__(256) void gemm_kernel(
    const float* __restrict__ x,      // [128,512]
    const float* __restrict__ W)      // [3072,512]
{
    __shared__ float sA[2][GBK][GBM + 4];   // 16.9 KB
    __shared__ float sB[2][GBK][GBN + 4];   // 16.9 KB

    const int bn = blockIdx.x * GBN;
    const int z  = blockIdx.y;                        // 0..5
    // balanced k split: z<2 -> 96 wide (6 tiles), z>=2 -> 80 wide (5 tiles)
    const int k_lo = (z < 2) ? z * 96 : 192 + (z - 2) * 80;
    const int nkt  = (z < 2) ? 6 : 5;

    const int t    = threadIdx.x;
    const int wid  = t >> 5;
    const int lane = t & 31;
    const int wm = wid >> 2;              // 0..1  (64 rows each)
    const int wn = wid & 3;               // 0..3  (32 cols each)
    const int mt = lane & 7;              // 0..7  -> 8 rows
    const int nt = lane >> 3;             // 0..3  -> 8 cols
    const int arow = wm * 64 + mt * 8;
    const int bcol = wn * 32 + nt * 8;

    // loader indices: tiles are 128x16 -> each thread loads 2 contiguous float4
    const int lr = t >> 1;                // 0..127
    const int lk = (t & 1) * 8;           // 0 or 8

    const float* pA = x + (size_t)lr * I_ + k_lo + lk;
    const float* pB = W + (size_t)(bn + lr) * I_ + k_lo + lk;

    float4 a0, a1, b0, b1;

    // prologue: tile0 -> buf0, prefetch tile1 -> regs
    a0 = __ldg((const float4*)pA);       a1 = __ldg((const float4*)(pA + 4));
    b0 = __ldg((const float4*)pB);       b1 = __ldg((const float4*)(pB + 4));
    sA[0][lk + 0][lr] = a0.x; sA[0][lk + 1][lr] = a0.y; sA[0][lk + 2][lr] = a0.z; sA[0][lk + 3][lr] = a0.w;
    sA[0][lk + 4][lr] = a1.x; sA[0][lk + 5][lr] = a1.y; sA[0][lk + 6][lr] = a1.z; sA[0][lk + 7][lr] = a1.w;
    sB[0][lk + 0][lr] = b0.x; sB[0][lk + 1][lr] = b0.y; sB[0][lk + 2][lr] = b0.z; sB[0][lk + 3][lr] = b0.w;
    sB[0][lk + 4][lr] = b1.x; sB[0][lk + 5][lr] = b1.y; sB[0][lk + 6][lr] = b1.z; sB[0][lk + 7][lr] = b1.w;
    a0 = __ldg((const float4*)(pA + GBK));  a1 = __ldg((const float4*)(pA + GBK + 4));
    b0 = __ldg((const float4*)(pB + GBK));  b1 = __ldg((const float4*)(pB + GBK + 4));
    __syncthreads();

    float acc[8][8] = {};

    for (int kt = 0; kt < nkt; kt++) {
        const int cur = kt & 1;
        if (kt < nkt - 1) {
            const int nxt = 1 - cur;
            sA[nxt][lk + 0][lr] = a0.x; sA[nxt][lk + 1][lr] = a0.y; sA[nxt][lk + 2][lr] = a0.z; sA[nxt][lk + 3][lr] = a0.w;
            sA[nxt][lk + 4][lr] = a1.x; sA[nxt][lk + 5][lr] = a1.y; sA[nxt][lk + 6][lr] = a1.z; sA[nxt][lk + 7][lr] = a1.w;
            sB[nxt][lk + 0][lr] = b0.x; sB[nxt][lk + 1][lr] = b0.y; sB[nxt][lk + 2][lr] = b0.z; sB[nxt][lk + 3][lr] = b0.w;
            sB[nxt][lk + 4][lr] = b1.x; sB[nxt][lk + 5][lr] = b1.y; sB[nxt][lk + 6][lr] = b1.z; sB[nxt][lk + 7][lr] = b1.w;
            if (kt < nkt - 2) {
                const int ko = (kt + 2) * GBK;
                a0 = __ldg((const float4*)(pA + ko));  a1 = __ldg((const float4*)(pA + ko + 4));
                b0 = __ldg((const float4*)(pB + ko));  b1 = __ldg((const float4*)(pB + ko + 4));
            }
        }

        #pragma unroll
        for (int k = 0; k < GBK; k++) {
            float4 av0 = *reinterpret_cast<const float4*>(&sA[cur][k][arow]);
            float4 av1 = *reinterpret_cast<const float4*>(&sA[cur][k][arow + 4]);
            float4 bv0 = *reinterpret_cast<const float4*>(&sB[cur][k][bcol]);
            float4 bv1 = *reinterpret_cast<const float4*>(&sB[cur][k][bcol + 4]);
            float a[8] = {av0.x, av0.y, av0.z, av0.w, av1.x, av1.y, av1.z, av1.w};
            float b[8] = {bv0.x, bv0.y, bv0.z, bv0.w, bv1.x, bv1.y, bv1.z, bv1.w};
            #pragma unroll
            for (int i = 0; i < 8; i++)
                #pragma unroll
                for (int j = 0; j < 8; j++)
                    acc[i][j] = fmaf(a[i], b[j], acc[i][j]);
        }
        __syncthreads();
    }

    float* out = g_part[z];
    #pragma unroll
    for (int i = 0; i < 8; i++) {
        float* row = out + (size_t)(arow + i) * SIXH + bn + bcol;
        *reinterpret_cast<float4*>(row)     = make_float4(acc[i][0], acc[i][1], acc[i][2], acc[i][3]);
        *reinterpret_cast<float4*>(row + 4) = make_float4(acc[i][4], acc[i][5], acc[i][6], acc[i][7]);
    }
}

// ---------------- Kernel 2: gate transforms + n.q reduction (PDL over gemm) ----
// One block per batch b, 512 threads (one per h). gate order: ig,fg,og,q,k,v.
// Independent inputs (m_prev/n_prev/bias) are loaded BEFORE the grid dependency
// barrier so they overlap the gemm tail.
__global__ __launch_bounds__(512) void gate_kernel(
    const float* __restrict__ m_prev,
    const float* __restrict__ n_prev,
    const float* __restrict__ bias,
    float* __restrict__ out_m,
    float* __restrict__ out_n)
{
    const int b = blockIdx.x;
    const int h = threadIdx.x;
    const int base = b * SIXH;
    const int idx = b * H_ + h;

    // prologue loads independent of gemm output
    float mp = m_prev[idx];
    float np = n_prev[idx];
    float bs[6];
    #pragma unroll
    for (int gi = 0; gi < 6; gi++) bs[gi] = bias[gi * H_ + h];

    cudaGridDependencySynchronize();   // wait for gemm partials

    float g[6];
    #pragma unroll
    for (int gi = 0; gi < 6; gi++) {
        int off = base + gi * H_ + h;
        float s01 = g_part[0][off] + g_part[1][off];
        float s23 = g_part[2][off] + g_part[3][off];
        float s45 = g_part[4][off] + g_part[5][off];
        g[gi] = ((s01 + s23) + s45) + bs[gi];
    }
    float ig = g[0], fg = g[1], og = g[2], qv = g[3], kk = g[4], vv = g[5];

    float mt = fmaxf(fg + mp, ig);
    float it = expf(ig - mt);
    float ft = expf(fg + mp - mt);
    float kt = 0.04419417382415922f * kk;   // 1/sqrt(512)
    float nt = ft * np + it * kt;

    out_m[idx] = mt;
    out_n[idx] = nt;
    g_f[idx]   = ft;
    g_add[idx] = it * vv * kt;
    g_o[idx]   = 1.0f / (1.0f + expf(-og));
    g_q[idx]   = qv;

    // deterministic block reduce of nt*qv over 512 threads
    float s = nt * qv;
    #pragma unroll
    for (int off = 16; off; off >>= 1) s += __shfl_xor_sync(0xffffffffu, s, off);

    __shared__ float red[16];
    int w = threadIdx.x >> 5, lane = threadIdx.x & 31;
    if (lane == 0) red[w] = s;
    __syncthreads();
    if (threadIdx.x == 0) {
        float tsum = 0.f;
        #pragma unroll
        for (int i = 0; i < 16; i++) tsum += red[i];
        g_denom[b] = fmaxf(fabsf(tsum), 1e-6f);
    }
}

// ---------------- Kernel 3: C_t update + readout + h_t (PDL over gate) ---------
// One warp per (b,i) row of 512 floats; 8 warps per block; q[b] staged in smem.
// C_prev loads (the DRAM-bound stream) are issued BEFORE the grid dependency
// barrier -> first-wave loads overlap gate (and gemm tail via chained PDL).
__global__ __launch_bounds__(256) void cmain_kernel(
    const float* __restrict__ C_prev,
    float* __restrict__ out_C,
    float* __restrict__ out_h)
{
    __shared__ float sq[H_];
    const int b = blockIdx.x >> 6;            // 64 blocks per batch
    const int row0 = (blockIdx.x & 63) * 8;

    const int w = threadIdx.x >> 5;
    const int lane = threadIdx.x & 31;
    const int i = row0 + w;
    const int bi = b * H_ + i;

    const float4* Cp = reinterpret_cast<const float4*>(C_prev) + (size_t)bi * (H_ / 4);
    float4*       Co = reinterpret_cast<float4*>(out_C)        + (size_t)bi * (H_ / 4);

    // issue the big DRAM reads before waiting on the upstream grid
    float4 c[4];
    #pragma unroll
    for (int t = 0; t < 4; t++) c[t] = __ldcs(Cp + lane + t * 32);

    cudaGridDependencySynchronize();   // wait for gate outputs

    const float* q = g_q + b * H_;
    for (int h = threadIdx.x; h < H_; h += 256) sq[h] = q[h];
    __syncthreads();

    const float f   = g_f[bi];
    const float add = g_add[bi];
    const float4* q4 = reinterpret_cast<const float4*>(sq);

    float acc = 0.f;
    #pragma unroll
    for (int t = 0; t < 4; t++) {
        int j4 = lane + t * 32;
        float4 r;
        r.x = fmaf(f, c[t].x, add);
        r.y = fmaf(f, c[t].y, add);
        r.z = fmaf(f, c[t].z, add);
        r.w = fmaf(f, c[t].w, add);
        __stcs(Co + j4, r);
        float4 qq = q4[j4];
        acc += r.x * qq.x + r.y * qq.y + r.z * qq.z + r.w * qq.w;
    }

    #pragma unroll
    for (int off = 16; off; off >>= 1) acc += __shfl_xor_sync(0xffffffffu, acc, off);

    if (lane == 0)
        out_h[bi] = g_o[bi] * acc / g_denom[b];
}

// ---------------- launch: serial stream + PDL overlap --------------------------
extern "C" void kernel_launch(void* const* d_in, const int* in_sizes, int n_in,
                              void* d_out, int out_size)
{
    const float* x      = (const float*)d_in[0];
    // d_in[1] = h_prev (unused by the reference)
    const float* C_prev = (const float*)d_in[2];
    const float* m_prev = (const float*)d_in[3];
    const float* n_prev = (const float*)d_in[4];
    const float* W      = (const float*)d_in[5];
    const float* bias   = (const float*)d_in[6];

    float* out   = (float*)d_out;
    float* out_h = out;                       // [B,H]
    float* out_C = out + BH;                  // [B,H,H]
    float* out_m = out + BH + CSZ;            // [B,H]
    float* out_n = out + BH + CSZ + BH;       // [B,H]

    // 1) GEMM (plain launch)
    dim3 ggrid(SIXH / GBN, NSPLIT);           // (24, 6) = 144 blocks = one wave
    gemm_kernel<<<ggrid, 256>>>(x, W);

    // 2) gate with programmatic stream serialization (overlaps gemm tail)
    {
        cudaLaunchConfig_t cfg = {};
        cfg.gridDim = dim3(B_);
        cfg.blockDim = dim3(512);
        cfg.stream = 0;
        cudaLaunchAttribute attr[1];
        attr[0].id = cudaLaunchAttributeProgrammaticStreamSerialization;
        attr[0].val.programmaticStreamSerializationAllowed = 1;
        cfg.attrs = attr;
        cfg.numAttrs = 1;
        cudaLaunchKernelEx(&cfg, gate_kernel, m_prev, n_prev, bias, out_m, out_n);
    }

    // 3) cmain with programmatic stream serialization (C_prev loads overlap gate)
    {
        cudaLaunchConfig_t cfg = {};
        cfg.gridDim = dim3(B_ * 64);
        cfg.blockDim = dim3(256);
        cfg.stream = 0;
        cudaLaunchAttribute attr[1];
        attr[0].id = cudaLaunchAttributeProgrammaticStreamSerialization;
        attr[0].val.programmaticStreamSerializationAllowed = 1;
        cfg.attrs = attr;
        cfg.numAttrs = 1;
        cudaLaunchKernelEx(&cfg, cmain_kernel, C_prev, out_C, out_h);
    }
}

// round 14
// speedup vs baseline: 1.8723x; 1.0047x over previous
#include <cuda_runtime.h>
#include <cuda_bf16.h>
#include <cstdint>

// Problem constants
#define B_ 128
#define H_ 512
#define I_ 512
#define SIXH 3072
#define BH (B_ * H_)          // 65536
#define CSZ (B_ * H_ * H_)    // 33554432
#define NSPLIT 6

// ---------------- scratch (no allocs allowed) ----------------
__device__ float g_part[NSPLIT][B_ * SIXH];   // split-K partial gates
__device__ float g_f[BH];
__device__ float g_add[BH];
__device__ float g_o[BH];
__device__ float g_q[BH];
__device__ float g_denom[B_];

// ---------------- packed f32x2 helpers (sm_103a FFMA2 path) ----------------
__device__ __forceinline__ uint64_t pack2(float lo, float hi) {
    uint64_t r;
    asm("mov.b64 %0, {%1, %2};" : "=l"(r) : "f"(lo), "f"(hi));
    return r;
}
__device__ __forceinline__ void ffma2(uint64_t& acc, uint64_t a, uint64_t b) {
    asm("fma.rn.f32x2 %0, %1, %2, %0;" : "+l"(acc) : "l"(a), "l"(b));
}
__device__ __forceinline__ float2 unpack2(uint64_t v) {
    float2 r;
    asm("mov.b64 {%0, %1}, %2;" : "=f"(r.x), "=f"(r.y) : "l"(v));
    return r;
}

// ---------------- Kernel 1: partial gates = x @ W^T (FFMA2, split-K=6) --------
// M=128(b)=BM, N=3072(gate), K=512. NT gemm, both operands K-major.
// BM=128 x BN=128 tile, BK=16, 256 threads (8 warps), micro-tile 8x8 via
// 32 packed f32x2 accumulators/thread, double-buffered smem.
// Grid (24, 6) = 144 blocks = one wave. Balanced splits: 2x96 + 4x80.
#define GBM 128
#define GBN 128
#define GBK 16

__global__ __launch_bounds__(256) void gemm_kernel(
    const float* __restrict__ x,      // [128,512]
    const float* __restrict__ W)      // [3072,512]
{
    __shared__ float sA[2][GBK][GBM + 4];   // 16.9 KB
    __shared__ float sB[2][GBK][GBN + 4];   // 16.9 KB

    const int bn = blockIdx.x * GBN;
    const int z  = blockIdx.y;                        // 0..5
    // balanced k split: z<2 -> 96 wide (6 tiles), z>=2 -> 80 wide (5 tiles)
    const int k_lo = (z < 2) ? z * 96 : 192 + (z - 2) * 80;
    const int nkt  = (z < 2) ? 6 : 5;

    const int t    = threadIdx.x;
    const int wid  = t >> 5;
    const int lane = t & 31;
    const int wm = wid >> 2;              // 0..1  (64 rows each)
    const int wn = wid & 3;               // 0..3  (32 cols each)
    const int mt = lane & 7;              // 0..7  -> 8 rows
    const int nt = lane >> 3;             // 0..3  -> 8 cols
    const int arow = wm * 64 + mt * 8;
    const int bcol = wn * 32 + nt * 8;

    // loader indices: tiles are 128x16 -> each thread loads 2 contiguous float4
    const int lr = t >> 1;                // 0..127
    const int lk = (t & 1) * 8;           // 0 or 8

    const float* pA = x + (size_t)lr * I_ + k_lo + lk;
    const float* pB = W + (size_t)(bn + lr) * I_ + k_lo + lk;

    float4 a0, a1, b0, b1;

    // prologue: tile0 -> buf0, prefetch tile1 -> regs
    a0 = __ldg((const float4*)pA);       a1 = __ldg((const float4*)(pA + 4));
    b0 = __ldg((const float4*)pB);       b1 = __ldg((const float4*)(pB + 4));
    sA[0][lk + 0][lr] = a0.x; sA[0][lk + 1][lr] = a0.y; sA[0][lk + 2][lr] = a0.z; sA[0][lk + 3][lr] = a0.w;
    sA[0][lk + 4][lr] = a1.x; sA[0][lk + 5][lr] = a1.y; sA[0][lk + 6][lr] = a1.z; sA[0][lk + 7][lr] = a1.w;
    sB[0][lk + 0][lr] = b0.x; sB[0][lk + 1][lr] = b0.y; sB[0][lk + 2][lr] = b0.z; sB[0][lk + 3][lr] = b0.w;
    sB[0][lk + 4][lr] = b1.x; sB[0][lk + 5][lr] = b1.y; sB[0][lk + 6][lr] = b1.z; sB[0][lk + 7][lr] = b1.w;
    a0 = __ldg((const float4*)(pA + GBK));  a1 = __ldg((const float4*)(pA + GBK + 4));
    b0 = __ldg((const float4*)(pB + GBK));  b1 = __ldg((const float4*)(pB + GBK + 4));
    __syncthreads();

    // 8 rows x 4 column-pairs of packed accumulators
    uint64_t acc2[8][4];
    #pragma unroll
    for (int i = 0; i < 8; i++)
        #pragma unroll
        for (int j = 0; j < 4; j++) acc2[i][j] = 0ull;

    for (int kt = 0; kt < nkt; kt++) {
        const int cur = kt & 1;
        if (kt < nkt - 1) {
            const int nxt = 1 - cur;
            sA[nxt][lk + 0][lr] = a0.x; sA[nxt][lk + 1][lr] = a0.y; sA[nxt][lk + 2][lr] = a0.z; sA[nxt][lk + 3][lr] = a0.w;
            sA[nxt][lk + 4][lr] = a1.x; sA[nxt][lk + 5][lr] = a1.y; sA[nxt][lk + 6][lr] = a1.z; sA[nxt][lk + 7][lr] = a1.w;
            sB[nxt][lk + 0][lr] = b0.x; sB[nxt][lk + 1][lr] = b0.y; sB[nxt][lk + 2][lr] = b0.z; sB[nxt][lk + 3][lr] = b0.w;
            sB[nxt][lk + 4][lr] = b1.x; sB[nxt][lk + 5][lr] = b1.y; sB[nxt][lk + 6][lr] = b1.z; sB[nxt][lk + 7][lr] = b1.w;
            if (kt < nkt - 2) {
                const int ko = (kt + 2) * GBK;
                a0 = __ldg((const float4*)(pA + ko));  a1 = __ldg((const float4*)(pA + ko + 4));
                b0 = __ldg((const float4*)(pB + ko));  b1 = __ldg((const float4*)(pB + ko + 4));
            }
        }

        #pragma unroll
        for (int k = 0; k < GBK; k++) {
            float4 av0 = *reinterpret_cast<const float4*>(&sA[cur][k][arow]);
            float4 av1 = *reinterpret_cast<const float4*>(&sA[cur][k][arow + 4]);
            float4 bv0 = *reinterpret_cast<const float4*>(&sB[cur][k][bcol]);
            float4 bv1 = *reinterpret_cast<const float4*>(&sB[cur][k][bcol + 4]);
            uint64_t bp[4];
            bp[0] = pack2(bv0.x, bv0.y);
            bp[1] = pack2(bv0.z, bv0.w);
            bp[2] = pack2(bv1.x, bv1.y);
            bp[3] = pack2(bv1.z, bv1.w);
            float a[8] = {av0.x, av0.y, av0.z, av0.w, av1.x, av1.y, av1.z, av1.w};
            #pragma unroll
            for (int i = 0; i < 8; i++) {
                uint64_t ap = pack2(a[i], a[i]);
                #pragma unroll
                for (int j = 0; j < 4; j++)
                    ffma2(acc2[i][j], ap, bp[j]);
            }
        }
        __syncthreads();
    }

    float* out = g_part[z];
    #pragma unroll
    for (int i = 0; i < 8; i++) {
        float2 p0 = unpack2(acc2[i][0]);
        float2 p1 = unpack2(acc2[i][1]);
        float2 p2 = unpack2(acc2[i][2]);
        float2 p3 = unpack2(acc2[i][3]);
        float* row = out + (size_t)(arow + i) * SIXH + bn + bcol;
        *reinterpret_cast<float4*>(row)     = make_float4(p0.x, p0.y, p1.x, p1.y);
        *reinterpret_cast<float4*>(row + 4) = make_float4(p2.x, p2.y, p3.x, p3.y);
    }
}

// ---------------- Kernel 2: gate transforms + n.q reduction (PDL over gemm) ----
__global__ __launch_bounds__(512) void gate_kernel(
    const float* __restrict__ m_prev,
    const float* __restrict__ n_prev,
    const float* __restrict__ bias,
    float* __restrict__ out_m,
    float* __restrict__ out_n)
{
    const int b = blockIdx.x;
    const int h = threadIdx.x;
    const int base = b * SIXH;
    const int idx = b * H_ + h;

    // prologue loads independent of gemm output
    float mp = m_prev[idx];
    float np = n_prev[idx];
    float bs[6];
    #pragma unroll
    for (int gi = 0; gi < 6; gi++) bs[gi] = bias[gi * H_ + h];

    cudaGridDependencySynchronize();   // wait for gemm partials

    float g[6];
    #pragma unroll
    for (int gi = 0; gi < 6; gi++) {
        int off = base + gi * H_ + h;
        float s01 = g_part[0][off] + g_part[1][off];
        float s23 = g_part[2][off] + g_part[3][off];
        float s45 = g_part[4][off] + g_part[5][off];
        g[gi] = ((s01 + s23) + s45) + bs[gi];
    }
    float ig = g[0], fg = g[1], og = g[2], qv = g[3], kk = g[4], vv = g[5];

    float mt = fmaxf(fg + mp, ig);
    float it = expf(ig - mt);
    float ft = expf(fg + mp - mt);
    float kt = 0.04419417382415922f * kk;   // 1/sqrt(512)
    float nt = ft * np + it * kt;

    out_m[idx] = mt;
    out_n[idx] = nt;
    g_f[idx]   = ft;
    g_add[idx] = it * vv * kt;
    g_o[idx]   = 1.0f / (1.0f + expf(-og));
    g_q[idx]   = qv;

    // deterministic block reduce of nt*qv over 512 threads
    float s = nt * qv;
    #pragma unroll
    for (int off = 16; off; off >>= 1) s += __shfl_xor_sync(0xffffffffu, s, off);

    __shared__ float red[16];
    int w = threadIdx.x >> 5, lane = threadIdx.x & 31;
    if (lane == 0) red[w] = s;
    __syncthreads();
    if (threadIdx.x == 0) {
        float tsum = 0.f;
        #pragma unroll
        for (int i = 0; i < 16; i++) tsum += red[i];
        g_denom[b] = fmaxf(fabsf(tsum), 1e-6f);
    }
}

// ---------------- Kernel 3: C_t update + readout + h_t (PDL over gate) ---------
__global__ __launch_bounds__(256) void cmain_kernel(
    const float* __restrict__ C_prev,
    float* __restrict__ out_C,
    float* __restrict__ out_h)
{
    __shared__ float sq[H_];
    const int b = blockIdx.x >> 6;            // 64 blocks per batch
    const int row0 = (blockIdx.x & 63) * 8;

    const int w = threadIdx.x >> 5;
    const int lane = threadIdx.x & 31;
    const int i = row0 + w;
    const int bi = b * H_ + i;

    const float4* Cp = reinterpret_cast<const float4*>(C_prev) + (size_t)bi * (H_ / 4);
    float4*       Co = reinterpret_cast<float4*>(out_C)        + (size_t)bi * (H_ / 4);

    // issue the big DRAM reads before waiting on the upstream grid
    float4 c[4];
    #pragma unroll
    for (int t = 0; t < 4; t++) c[t] = __ldcs(Cp + lane + t * 32);

    cudaGridDependencySynchronize();   // wait for gate outputs

    const float* q = g_q + b * H_;
    for (int h = threadIdx.x; h < H_; h += 256) sq[h] = q[h];
    __syncthreads();

    const float f   = g_f[bi];
    const float add = g_add[bi];
    const float4* q4 = reinterpret_cast<const float4*>(sq);

    float acc = 0.f;
    #pragma unroll
    for (int t = 0; t < 4; t++) {
        int j4 = lane + t * 32;
        float4 r;
        r.x = fmaf(f, c[t].x, add);
        r.y = fmaf(f, c[t].y, add);
        r.z = fmaf(f, c[t].z, add);
        r.w = fmaf(f, c[t].w, add);
        __stcs(Co + j4, r);
        float4 qq = q4[j4];
        acc += r.x * qq.x + r.y * qq.y + r.z * qq.z + r.w * qq.w;
    }

    #pragma unroll
    for (int off = 16; off; off >>= 1) acc += __shfl_xor_sync(0xffffffffu, acc, off);

    if (lane == 0)
        out_h[bi] = g_o[bi] * acc / g_denom[b];
}

// ---------------- launch: serial stream + PDL overlap --------------------------
extern "C" void kernel_launch(void* const* d_in, const int* in_sizes, int n_in,
                              void* d_out, int out_size)
{
    const float* x      = (const float*)d_in[0];
    // d_in[1] = h_prev (unused by the reference)
    const float* C_prev = (const float*)d_in[2];
    const float* m_prev = (const float*)d_in[3];
    const float* n_prev = (const float*)d_in[4];
    const float* W      = (const float*)d_in[5];
    const float* bias   = (const float*)d_in[6];

    float* out   = (float*)d_out;
    float* out_h = out;                       // [B,H]
    float* out_C = out + BH;                  // [B,H,H]
    float* out_m = out + BH + CSZ;            // [B,H]
    float* out_n = out + BH + CSZ + BH;       // [B,H]

    // 1) GEMM (plain launch)
    dim3 ggrid(SIXH / GBN, NSPLIT);           // (24, 6) = 144 blocks = one wave
    gemm_kernel<<<ggrid, 256>>>(x, W);

    // 2) gate with programmatic stream serialization (overlaps gemm tail)
    {
        cudaLaunchConfig_t cfg = {};
        cfg.gridDim = dim3(B_);
        cfg.blockDim = dim3(512);
        cfg.stream = 0;
        cudaLaunchAttribute attr[1];
        attr[0].id = cudaLaunchAttributeProgrammaticStreamSerialization;
        attr[0].val.programmaticStreamSerializationAllowed = 1;
        cfg.attrs = attr;
        cfg.numAttrs = 1;
        cudaLaunchKernelEx(&cfg, gate_kernel, m_prev, n_prev, bias, out_m, out_n);
    }

    // 3) cmain with programmatic stream serialization (C_prev loads overlap gate)
    {
        cudaLaunchConfig_t cfg = {};
        cfg.gridDim = dim3(B_ * 64);
        cfg.blockDim = dim3(256);
        cfg.stream = 0;
        cudaLaunchAttribute attr[1];
        attr[0].id = cudaLaunchAttributeProgrammaticStreamSerialization;
        attr[0].val.programmaticStreamSerializationAllowed = 1;
        cfg.attrs = attr;
        cfg.numAttrs = 1;
        cudaLaunchKernelEx(&cfg, cmain_kernel, C_prev, out_C, out_h);
    }
}